// round 1
// baseline (speedup 1.0000x reference)
#include <cuda_runtime.h>

// Problem constants
#define B_SZ   64
#define T_STEPS 1000
#define IN_F   512
#define OUT_F  512
#define M_TOTAL (B_SZ * T_STEPS)   // 64000

// Scratch (device globals: allocation-free at launch time)
__device__ float g_cur[(size_t)M_TOTAL * OUT_F];   // [b*T + t][o], 131 MB
__device__ float g_Rt[OUT_F * OUT_F];              // Rt[j][o] = R[o][j]

// ---------------------------------------------------------------------------
// R transpose: Rt[j][o] = R[o][j]  (so per-spike row gather is coalesced)
// ---------------------------------------------------------------------------
__global__ void transpose_kernel(const float* __restrict__ R) {
    __shared__ float tile[32][33];
    int jx = blockIdx.x * 32 + threadIdx.x;   // j (column of R)
    int oy = blockIdx.y * 32 + threadIdx.y;   // o (row of R)
    #pragma unroll
    for (int dy = 0; dy < 32; dy += 8)
        tile[threadIdx.y + dy][threadIdx.x] = R[(size_t)(oy + dy) * OUT_F + jx];
    __syncthreads();
    int ox = blockIdx.y * 32 + threadIdx.x;
    int jy = blockIdx.x * 32 + threadIdx.y;
    #pragma unroll
    for (int dy = 0; dy < 32; dy += 8)
        g_Rt[(size_t)(jy + dy) * OUT_F + ox] = tile[threadIdx.x][threadIdx.y + dy];
}

// ---------------------------------------------------------------------------
// Input GEMM: g_cur[m][n] = bias[n] + sum_k x[m][k] * W[n][k]
// M=64000, N=512, K=512.  128x128 block tile, BK=8, 256 threads, 8x8/thread.
// ---------------------------------------------------------------------------
#define BM 128
#define BN 128
#define BK 8
#define TM 8
#define TN 8

__global__ __launch_bounds__(256) void gemm_kernel(
    const float* __restrict__ A,     // x      [M][512]
    const float* __restrict__ W,     // weight [512][512]
    const float* __restrict__ bias)  // [512]
{
    __shared__ float As[BK][BM];
    __shared__ float Bs[BK][BN];

    const int tid   = threadIdx.x;
    const int mBase = blockIdx.y * BM;
    const int nBase = blockIdx.x * BN;

    // one float4 of A and one of W per thread per K-block
    const int loadRow = tid >> 1;         // 0..127
    const int loadCol = (tid & 1) * 4;    // 0 or 4

    const int tRow = (tid >> 4) * TM;     // 0..120
    const int tCol = (tid & 15) * TN;     // 0..120

    float acc[TM][TN];
    #pragma unroll
    for (int i = 0; i < TM; i++)
        #pragma unroll
        for (int j = 0; j < TN; j++)
            acc[i][j] = 0.f;

    const float* aPtr = A + (size_t)(mBase + loadRow) * IN_F + loadCol;
    const float* wPtr = W + (size_t)(nBase + loadRow) * IN_F + loadCol;

    for (int k0 = 0; k0 < IN_F; k0 += BK) {
        float4 a4 = *(const float4*)(aPtr + k0);
        float4 b4 = *(const float4*)(wPtr + k0);
        As[loadCol + 0][loadRow] = a4.x;
        As[loadCol + 1][loadRow] = a4.y;
        As[loadCol + 2][loadRow] = a4.z;
        As[loadCol + 3][loadRow] = a4.w;
        Bs[loadCol + 0][loadRow] = b4.x;
        Bs[loadCol + 1][loadRow] = b4.y;
        Bs[loadCol + 2][loadRow] = b4.z;
        Bs[loadCol + 3][loadRow] = b4.w;
        __syncthreads();

        #pragma unroll
        for (int kk = 0; kk < BK; kk++) {
            float4 m0 = *(const float4*)&As[kk][tRow];
            float4 m1 = *(const float4*)&As[kk][tRow + 4];
            float4 n0 = *(const float4*)&Bs[kk][tCol];
            float4 n1 = *(const float4*)&Bs[kk][tCol + 4];
            float rm[TM] = {m0.x, m0.y, m0.z, m0.w, m1.x, m1.y, m1.z, m1.w};
            float rn[TN] = {n0.x, n0.y, n0.z, n0.w, n1.x, n1.y, n1.z, n1.w};
            #pragma unroll
            for (int i = 0; i < TM; i++)
                #pragma unroll
                for (int j = 0; j < TN; j++)
                    acc[i][j] = fmaf(rm[i], rn[j], acc[i][j]);
        }
        __syncthreads();
    }

    float4 bz0 = *(const float4*)(bias + nBase + tCol);
    float4 bz1 = *(const float4*)(bias + nBase + tCol + 4);

    #pragma unroll
    for (int i = 0; i < TM; i++) {
        size_t row = (size_t)(mBase + tRow + i);
        float4 s0 = make_float4(acc[i][0] + bz0.x, acc[i][1] + bz0.y,
                                acc[i][2] + bz0.z, acc[i][3] + bz0.w);
        float4 s1 = make_float4(acc[i][4] + bz1.x, acc[i][5] + bz1.y,
                                acc[i][6] + bz1.z, acc[i][7] + bz1.w);
        *(float4*)&g_cur[row * OUT_F + nBase + tCol]     = s0;
        *(float4*)&g_cur[row * OUT_F + nBase + tCol + 4] = s1;
    }
}

// ---------------------------------------------------------------------------
// Sequential ALIF scan: 1 CTA per batch element, 1 thread per neuron.
// z is binary -> kept as 16 ballot words in smem; recurrent matmul iterates
// only set bits (spike rate expected ~0).
// ---------------------------------------------------------------------------
__global__ __launch_bounds__(OUT_F) void scan_kernel(
    const float* __restrict__ beta,
    const float* __restrict__ beta2,
    const float* __restrict__ decay_v,
    const float* __restrict__ decay_b,
    float* __restrict__ out,
    int write_states)
{
    const int b    = blockIdx.x;
    const int o    = threadIdx.x;
    const int warp = o >> 5;
    const int lane = o & 31;

    __shared__ unsigned zmask[OUT_F / 32];   // ballot of carry z

    const float bt  = beta[o];
    const float bt2 = beta2[o];
    const float dv  = decay_v[o];
    const float db  = decay_b[o];
    const float odv = 1.f - dv;
    const float odb = 1.f - db;

    float v = 0.f, z = 0.f, ba = 0.f;

    // Output layout: concat( zs[B][T][O], v_full[B][T+1][O], z_full[..], b_full[..] )
    float* zs   = out;
    float* vful = out + (size_t)B_SZ * T_STEPS * OUT_F;
    float* zful = vful + (size_t)B_SZ * (T_STEPS + 1) * OUT_F;
    float* bful = zful + (size_t)B_SZ * (T_STEPS + 1) * OUT_F;

    if (write_states) {
        size_t p = (size_t)b * (T_STEPS + 1) * OUT_F + o;   // t = 0 pad rows
        vful[p] = 0.f; zful[p] = 0.f; bful[p] = 0.f;
    }

    const float* curb = g_cur + ((size_t)b * T_STEPS) * OUT_F + o;
    float c0 = curb[0];
    float c1 = curb[OUT_F];

    if (lane == 0) zmask[warp] = 0u;   // z_{-1} = 0
    __syncthreads();

    size_t zsIdx = ((size_t)b * T_STEPS) * OUT_F + o;
    size_t stIdx = ((size_t)b * (T_STEPS + 1) + 1) * OUT_F + o;

    for (int t = 0; t < T_STEPS; t++) {
        // prefetch cur two steps ahead (covers DRAM latency)
        float cnext = (t + 2 < T_STEPS) ? curb[(size_t)(t + 2) * OUT_F] : 0.f;

        // recurrent input: sum over active presynaptic neurons (prev-step z)
        float rec = 0.f;
        #pragma unroll
        for (int w = 0; w < OUT_F / 32; w++) {
            unsigned m = zmask[w];
            while (m) {
                int j = (w << 5) + (__ffs(m) - 1);
                m &= m - 1;
                rec += g_Rt[(size_t)j * OUT_F + o];
            }
        }

        float cc = c0 + rec;
        v  = v * (1.f - z);                 // reset with previous z
        v  = dv * v + odv * (cc - ba);      // membrane update (previous b)
        z  = (v >= 1.f) ? 1.f : 0.f;        // THR = 1.0, forward spike is Heaviside
        ba = db * ba + odb * (bt * v + bt2 * z);

        zs[zsIdx] = z;
        if (write_states) {
            vful[stIdx] = v;
            zful[stIdx] = z;
            bful[stIdx] = ba;
        }

        unsigned ball = __ballot_sync(0xffffffffu, z >= 1.f);
        __syncthreads();                    // all readers done with old masks
        if (lane == 0) zmask[warp] = ball;
        __syncthreads();                    // new masks visible

        c0 = c1; c1 = cnext;
        zsIdx += OUT_F;
        stIdx += OUT_F;
    }
}

// ---------------------------------------------------------------------------
extern "C" void kernel_launch(void* const* d_in, const int* in_sizes, int n_in,
                              void* d_out, int out_size) {
    const float* x     = (const float*)d_in[0];
    const float* wgt   = (const float*)d_in[1];
    const float* bias  = (const float*)d_in[2];
    const float* rec   = (const float*)d_in[3];
    const float* beta  = (const float*)d_in[4];
    const float* beta2 = (const float*)d_in[5];
    const float* dv    = (const float*)d_in[6];
    const float* db    = (const float*)d_in[7];
    float* out = (float*)d_out;

    dim3 tb(32, 8), tg(16, 16);
    transpose_kernel<<<tg, tb>>>(rec);

    dim3 gg(OUT_F / BN, M_TOTAL / BM);
    gemm_kernel<<<gg, 256>>>(x, wgt, bias);

    // Defensive: if the harness only wants zs, skip state writes.
    int write_states = (out_size > B_SZ * T_STEPS * OUT_F) ? 1 : 0;
    scan_kernel<<<B_SZ, OUT_F>>>(beta, beta2, dv, db, out, write_states);
}